// round 16
// baseline (speedup 1.0000x reference)
#include <cuda_runtime.h>
#include <math.h>
#include <stdint.h>
#include <stddef.h>

// Problem constants
#define Bb   16
#define Nn   4096
#define Ss   1024
#define C1c  128
#define C2c  256
#define CINc 384
#define COc  128
#define Mm   (Bb * Nn)          // 65536 rows

// ---------------------------------------------------------------------------
// Scratch (static __device__ arrays: no allocations anywhere)
// ---------------------------------------------------------------------------
__device__ float g_np [(size_t)Mm * CINc];   // new_points (M,384)
__device__ float g_y1 [(size_t)Mm * COc];    // conv1 pre-BN
__device__ float g_x  [(size_t)Mm * COc];    // gelu(bn(y1)) residual
__device__ float g_y2 [(size_t)Mm * COc];    // conv2 pre-BN
__device__ float g_y3 [(size_t)Mm * COc];    // conv3 pre-BN
__device__ int   g_idx[Mm * 3];
__device__ float g_w  [Mm * 3];
__device__ float g_Wt1[CINc * COc];          // fuse_w transposed  [k][o]
__device__ float g_Wt2[COc * COc];           // w1 transposed
__device__ float g_Wt3[COc * COc];           // w2 transposed
__device__ float g_sum[3][COc];
__device__ float g_ssq[3][COc];
__device__ float g_bna[3][COc];              // BN scale  (g * invstd)
__device__ float g_bnb[3][COc];              // BN shift  (bt - mean * scale)

__device__ __forceinline__ float gelu_f(float v) {
    return v * (0.5f * (1.0f + erff(v * 0.70710678118654752f)));
}

// ---------------------------------------------------------------------------
// Prep: zero stats + transpose weights (tiny)
// ---------------------------------------------------------------------------
__global__ void prep_kernel(const float* __restrict__ fuse_w,
                            const float* __restrict__ w1,
                            const float* __restrict__ w2) {
    int i = blockIdx.x * blockDim.x + threadIdx.x;   // 49152 threads
    if (i < CINc * COc) {
        int k = i / COc, o = i % COc;
        g_Wt1[i] = fuse_w[o * CINc + k];
    }
    if (i < COc * COc) {
        int k = i / COc, o = i % COc;
        g_Wt2[i] = w1[o * COc + k];
        g_Wt3[i] = w2[o * COc + k];
    }
    if (i < 3 * COc) {
        (&g_sum[0][0])[i] = 0.0f;
        (&g_ssq[0][0])[i] = 0.0f;
    }
}

// ---------------------------------------------------------------------------
// 3-NN: one thread per query point, xyz2 batch tile in smem
// grid (N/256, B), block 256
// ---------------------------------------------------------------------------
__global__ void knn_kernel(const float* __restrict__ xyz1,
                           const float* __restrict__ xyz2) {
    __shared__ float sx[Ss], sy[Ss], sz[Ss], sn[Ss];
    const int b = blockIdx.y;
    const float* p2 = xyz2 + (size_t)b * Ss * 3;
    for (int s = threadIdx.x; s < Ss; s += 256) {
        float x = p2[s * 3 + 0], y = p2[s * 3 + 1], z = p2[s * 3 + 2];
        sx[s] = x; sy[s] = y; sz[s] = z;
        sn[s] = x * x + y * y + z * z;
    }
    __syncthreads();

    const int n = blockIdx.x * 256 + threadIdx.x;
    const int p = b * Nn + n;
    const float x1 = xyz1[p * 3 + 0], y1 = xyz1[p * 3 + 1], z1 = xyz1[p * 3 + 2];
    const float n1 = x1 * x1 + y1 * y1 + z1 * z1;

    float d0 = 3.4e38f, d1 = 3.4e38f, d2 = 3.4e38f;
    int   i0 = 0, i1 = 0, i2 = 0;
    #pragma unroll 4
    for (int s = 0; s < Ss; ++s) {
        float dot = x1 * sx[s] + y1 * sy[s] + z1 * sz[s];
        float sq  = n1 + sn[s] - 2.0f * dot;     // reference expansion
        if (sq < d2) {
            if (sq < d1) {
                d2 = d1; i2 = i1;
                if (sq < d0) { d1 = d0; i1 = i0; d0 = sq; i0 = s; }
                else         { d1 = sq; i1 = s; }
            } else { d2 = sq; i2 = s; }
        }
    }
    float e0 = sqrtf(fmaxf(d0, 1e-12f));
    float e1 = sqrtf(fmaxf(d1, 1e-12f));
    float e2 = sqrtf(fmaxf(d2, 1e-12f));
    float r0 = 1.0f / (e0 + 1e-8f);
    float r1 = 1.0f / (e1 + 1e-8f);
    float r2 = 1.0f / (e2 + 1e-8f);
    float rs = r0 + r1 + r2;
    g_idx[p * 3 + 0] = i0; g_idx[p * 3 + 1] = i1; g_idx[p * 3 + 2] = i2;
    g_w  [p * 3 + 0] = r0 / rs;
    g_w  [p * 3 + 1] = r1 / rs;
    g_w  [p * 3 + 2] = r2 / rs;
}

// ---------------------------------------------------------------------------
// Build new_points = concat(points1, interp). One warp per point.
// grid 8192, block 256 (8 warps)
// ---------------------------------------------------------------------------
__global__ void interp_kernel(const float* __restrict__ points1,
                              const float* __restrict__ points2) {
    const int p    = ((blockIdx.x * 256 + threadIdx.x) >> 5);  // 0..65535
    const int lane = threadIdx.x & 31;
    const int b    = p >> 12;
    const int i0 = g_idx[p * 3 + 0], i1 = g_idx[p * 3 + 1], i2 = g_idx[p * 3 + 2];
    const float w0 = g_w[p * 3 + 0], w1 = g_w[p * 3 + 1], w2 = g_w[p * 3 + 2];

    float4*       o4 = (float4*)(g_np + (size_t)p * CINc);
    const float4* p1 = (const float4*)(points1 + (size_t)p * C1c);
    o4[lane] = p1[lane];                                       // 128 floats

    const float4* r0 = (const float4*)(points2 + ((size_t)b * Ss + i0) * C2c);
    const float4* r1 = (const float4*)(points2 + ((size_t)b * Ss + i1) * C2c);
    const float4* r2 = (const float4*)(points2 + ((size_t)b * Ss + i2) * C2c);
    #pragma unroll
    for (int c = lane; c < C2c / 4; c += 32) {
        float4 v0 = r0[c], v1 = r1[c], v2 = r2[c], o;
        o.x = fmaf(w2, v2.x, fmaf(w1, v1.x, w0 * v0.x));
        o.y = fmaf(w2, v2.y, fmaf(w1, v1.y, w0 * v0.y));
        o.z = fmaf(w2, v2.z, fmaf(w1, v1.z, w0 * v0.z));
        o.w = fmaf(w2, v2.w, fmaf(w1, v1.w, w0 * v0.w));
        o4[32 + c] = o;
    }
}

// ---------------------------------------------------------------------------
// SGEMM 128x128 tile, BK=8 double-buffered, 256 threads, 8x8 micro-tile.
// STAGE 0: A=g_np (K=384)                     -> y1, stats[0]
// STAGE 1: A=gelu(bn0(g_y1)) (K=128), store x -> y2, stats[1]
// STAGE 2: A=gelu(bn1(g_y2)) (K=128)          -> y3, stats[2]
// ---------------------------------------------------------------------------
template <int STAGE>
__global__ __launch_bounds__(256, 2) void gemm_stage(const float* __restrict__ bias) {
    constexpr int  K      = (STAGE == 0) ? CINc : COc;
    constexpr int  NT     = K / 8;
    constexpr bool FUSE   = (STAGE != 0);
    constexpr bool STOREX = (STAGE == 1);

    const float* __restrict__ A  = (STAGE == 0) ? g_np  : (STAGE == 1 ? g_y1 : g_y2);
    const float* __restrict__ Wt = (STAGE == 0) ? g_Wt1 : (STAGE == 1 ? g_Wt2 : g_Wt3);
    float*       __restrict__ Y  = (STAGE == 0) ? g_y1  : (STAGE == 1 ? g_y2 : g_y3);
    const float* __restrict__ BNA = g_bna[STAGE == 0 ? 0 : STAGE - 1];
    const float* __restrict__ BNB = g_bnb[STAGE == 0 ? 0 : STAGE - 1];
    float* SUM = g_sum[STAGE];
    float* SSQ = g_ssq[STAGE];

    __shared__ __align__(16) float As[2][8][128];
    __shared__ __align__(16) float Bs[2][8][128];

    const int t    = threadIdx.x;
    const int row0 = blockIdx.x * 128;
    const int am = t >> 1;             // A-load row within tile
    const int ak = (t & 1) * 4;        // A-load col (float4)
    const int bk = t >> 5;             // B-load k within tile
    const int bo = (t & 31) * 4;       // B-load out-channel (float4)
    const float* Ap = A  + (size_t)(row0 + am) * K + ak;
    const float* Bp = Wt + bk * COc + bo;

    auto xform = [&](float4& av, int kb0) {
        if constexpr (FUSE) {
            const int kb = kb0 + ak;
            float4 sa = *(const float4*)(BNA + kb);
            float4 sb = *(const float4*)(BNB + kb);
            av.x = gelu_f(fmaf(av.x, sa.x, sb.x));
            av.y = gelu_f(fmaf(av.y, sa.y, sb.y));
            av.z = gelu_f(fmaf(av.z, sa.z, sb.z));
            av.w = gelu_f(fmaf(av.w, sa.w, sb.w));
            if constexpr (STOREX)
                *(float4*)(g_x + (size_t)(row0 + am) * K + kb) = av;
        }
    };

    // Prologue: tile 0 -> buffer 0
    {
        float4 av = *(const float4*)Ap;
        float4 bv = *(const float4*)Bp;
        xform(av, 0);
        As[0][ak + 0][am] = av.x; As[0][ak + 1][am] = av.y;
        As[0][ak + 2][am] = av.z; As[0][ak + 3][am] = av.w;
        *(float4*)&Bs[0][bk][bo] = bv;
    }
    __syncthreads();

    float acc[8][8];
    #pragma unroll
    for (int i = 0; i < 8; ++i)
        #pragma unroll
        for (int j = 0; j < 8; ++j) acc[i][j] = 0.0f;

    const int tx = t & 15, ty = t >> 4;

    for (int kt = 0; kt < NT; ++kt) {
        const int cbuf = kt & 1;
        float4 av, bv;
        const bool more = (kt + 1) < NT;
        if (more) {
            av = *(const float4*)(Ap + (kt + 1) * 8);
            bv = *(const float4*)(Bp + (size_t)(kt + 1) * 8 * COc);
        }
        #pragma unroll
        for (int kk = 0; kk < 8; ++kk) {
            float af[8], bf[8];
            *(float4*)(af)     = *(const float4*)&As[cbuf][kk][ty * 8];
            *(float4*)(af + 4) = *(const float4*)&As[cbuf][kk][ty * 8 + 4];
            *(float4*)(bf)     = *(const float4*)&Bs[cbuf][kk][tx * 8];
            *(float4*)(bf + 4) = *(const float4*)&Bs[cbuf][kk][tx * 8 + 4];
            #pragma unroll
            for (int i = 0; i < 8; ++i)
                #pragma unroll
                for (int j = 0; j < 8; ++j)
                    acc[i][j] = fmaf(af[i], bf[j], acc[i][j]);
        }
        if (more) {
            xform(av, (kt + 1) * 8);
            const int nb = cbuf ^ 1;
            As[nb][ak + 0][am] = av.x; As[nb][ak + 1][am] = av.y;
            As[nb][ak + 2][am] = av.z; As[nb][ak + 3][am] = av.w;
            *(float4*)&Bs[nb][bk][bo] = bv;
        }
        __syncthreads();
    }

    // Epilogue: bias, store Y, per-channel partial stats
    const float4 bias0 = *(const float4*)(bias + tx * 8);
    const float4 bias1 = *(const float4*)(bias + tx * 8 + 4);
    float csum[8], cssq[8];
    #pragma unroll
    for (int j = 0; j < 8; ++j) { csum[j] = 0.0f; cssq[j] = 0.0f; }

    #pragma unroll
    for (int i = 0; i < 8; ++i) {
        const int row = row0 + ty * 8 + i;
        float v[8];
        v[0] = acc[i][0] + bias0.x; v[1] = acc[i][1] + bias0.y;
        v[2] = acc[i][2] + bias0.z; v[3] = acc[i][3] + bias0.w;
        v[4] = acc[i][4] + bias1.x; v[5] = acc[i][5] + bias1.y;
        v[6] = acc[i][6] + bias1.z; v[7] = acc[i][7] + bias1.w;
        *(float4*)(Y + (size_t)row * COc + tx * 8)     = make_float4(v[0], v[1], v[2], v[3]);
        *(float4*)(Y + (size_t)row * COc + tx * 8 + 4) = make_float4(v[4], v[5], v[6], v[7]);
        #pragma unroll
        for (int j = 0; j < 8; ++j) {
            csum[j] += v[j];
            cssq[j]  = fmaf(v[j], v[j], cssq[j]);
        }
    }

    // Block-level channel reduction (reuse As as 16x128 scratch), then atomics
    float* red = &As[0][0][0];
    #pragma unroll
    for (int j = 0; j < 8; ++j) red[ty * 128 + tx * 8 + j] = csum[j];
    __syncthreads();
    if (t < 128) {
        float s = 0.0f;
        #pragma unroll
        for (int r = 0; r < 16; ++r) s += red[r * 128 + t];
        atomicAdd(&SUM[t], s);
    }
    __syncthreads();
    #pragma unroll
    for (int j = 0; j < 8; ++j) red[ty * 128 + tx * 8 + j] = cssq[j];
    __syncthreads();
    if (t < 128) {
        float s = 0.0f;
        #pragma unroll
        for (int r = 0; r < 16; ++r) s += red[r * 128 + t];
        atomicAdd(&SSQ[t], s);
    }
}

// ---------------------------------------------------------------------------
// BN finalize: fold gamma/beta into affine (a, b)
// ---------------------------------------------------------------------------
__global__ void bn_finalize(int stage, const float* __restrict__ g,
                            const float* __restrict__ bt) {
    const int c = threadIdx.x;                 // 128
    const float invM = 1.0f / (float)Mm;
    float mean = g_sum[stage][c] * invM;
    float var  = g_ssq[stage][c] * invM - mean * mean;
    float inv  = rsqrtf(var + 1e-5f);
    float a    = g[c] * inv;
    g_bna[stage][c] = a;
    g_bnb[stage][c] = bt[c] - mean * a;
}

// ---------------------------------------------------------------------------
// Final: out = gelu(bn2(y3) + x)
// ---------------------------------------------------------------------------
__global__ void epilogue_kernel(float* __restrict__ out) {
    const int i4 = blockIdx.x * blockDim.x + threadIdx.x;  // 2,097,152 float4s
    const int c4 = (i4 & 31) * 4;
    float4 a  = *(const float4*)(&g_bna[2][c4]);
    float4 bb = *(const float4*)(&g_bnb[2][c4]);
    float4 y  = ((const float4*)g_y3)[i4];
    float4 x  = ((const float4*)g_x)[i4];
    float4 o;
    o.x = gelu_f(fmaf(y.x, a.x, bb.x) + x.x);
    o.y = gelu_f(fmaf(y.y, a.y, bb.y) + x.y);
    o.z = gelu_f(fmaf(y.z, a.z, bb.z) + x.z);
    o.w = gelu_f(fmaf(y.w, a.w, bb.w) + x.w);
    ((float4*)out)[i4] = o;
}

// ---------------------------------------------------------------------------
extern "C" void kernel_launch(void* const* d_in, const int* in_sizes, int n_in,
                              void* d_out, int out_size) {
    (void)in_sizes; (void)n_in; (void)out_size;
    const float* xyz1    = (const float*)d_in[0];
    const float* xyz2    = (const float*)d_in[1];
    const float* points1 = (const float*)d_in[2];
    const float* points2 = (const float*)d_in[3];
    const float* fuse_w  = (const float*)d_in[4];
    const float* fuse_b  = (const float*)d_in[5];
    const float* fuse_g  = (const float*)d_in[6];
    const float* fuse_bt = (const float*)d_in[7];
    const float* w1      = (const float*)d_in[8];
    const float* b1      = (const float*)d_in[9];
    const float* g1      = (const float*)d_in[10];
    const float* bt1     = (const float*)d_in[11];
    const float* w2      = (const float*)d_in[12];
    const float* b2      = (const float*)d_in[13];
    const float* g2      = (const float*)d_in[14];
    const float* bt2     = (const float*)d_in[15];
    float* out = (float*)d_out;

    prep_kernel<<<192, 256>>>(fuse_w, w1, w2);
    knn_kernel<<<dim3(Nn / 256, Bb), 256>>>(xyz1, xyz2);
    interp_kernel<<<Mm / 8, 256>>>(points1, points2);

    gemm_stage<0><<<Mm / 128, 256>>>(fuse_b);
    bn_finalize<<<1, 128>>>(0, fuse_g, fuse_bt);
    gemm_stage<1><<<Mm / 128, 256>>>(b1);
    bn_finalize<<<1, 128>>>(1, g1, bt1);
    gemm_stage<2><<<Mm / 128, 256>>>(b2);
    bn_finalize<<<1, 128>>>(2, g2, bt2);

    epilogue_kernel<<<(Mm * COc) / 4 / 256, 256>>>(out);
}